// round 13
// baseline (speedup 1.0000x reference)
#include <cuda_runtime.h>
#include <cuda_bf16.h>

// Problem constants
#define NXS    41
#define GTOT   68921          // 41^3
#define NX2    1681           // 41^2
#define NWORDS 2160           // dense mask words (tail zero)
#define CHUNKS 539            // chunk = 128 voxels (4 mask words)
#define KPK    4
#define NEGV   (-1.0e9f)
#define VTH    (-1.0e8f)
#define NPAIR  512            // B*N*C = 1*128*4
#define FULLM  0xffffffffu
#define NTHR   384            // 12 warps
#define NWARP  12

// Compile-time axis coords: float((i-20)*0.3 computed in double) — bit-exact vs numpy
struct AxTable { float v[NXS]; };
static constexpr AxTable make_ax()
{
    AxTable t{};
    for (int i = 0; i < NXS; ++i) t.v[i] = (float)((double)(i - 20) * 0.3);
    return t;
}
__constant__ AxTable c_ax = make_ax();

// Compile-time conservative non-empty chunk lists per alignment shift a (0..3).
// Superset of true in-sphere chunks -> safe (bounds are verified upper bounds).
struct ChunkLists { short list[4][CHUNKS]; int n[4]; };
static constexpr ChunkLists make_lists()
{
    ChunkLists L{};
    for (int a = 0; a < 4; ++a) {
        int cnt = 0;
        for (int c = 0; c < CHUNKS; ++c) {
            bool ne = false;
            for (int p = c * 128; p < c * 128 + 128 && !ne; ++p) {
                int g = p + a;
                if (g >= GTOT) break;
                int i = g / NX2, j = (g / NXS) % NXS, kk = g % NXS;
                double x = (i - 20) * 0.3, y = (j - 20) * 0.3, z = (kk - 20) * 0.3;
                if (x * x + y * y + z * z <= 36.01) ne = true;
            }
            if (ne) { L.list[a][cnt] = (short)c; ++cnt; }
        }
        L.n[a] = cnt;
    }
    return L;
}
__constant__ ChunkLists c_lists = make_lists();

// Dense sphere mask (exact fp32 semantics), tail words zero
__device__ unsigned int g_S0[NWORDS];

// ---------------------------------------------------------------------------
// Kernel 1: dense sphere mask, numpy-identical fp32 op sequence
// ---------------------------------------------------------------------------
__global__ __launch_bounds__(256) void init_masks_kernel()
{
    __shared__ float ax[NXS];
    if (threadIdx.x < NXS) ax[threadIdx.x] = c_ax.v[threadIdx.x];
    __syncthreads();
    int g = blockIdx.x * 256 + threadIdx.x;    // 270*256 = 69120 = 2160 words
    bool ok = false;
    if (g < GTOT) {
        int i = g / NX2;
        int j = (g / NXS) % NXS;
        int k = g % NXS;
        float x = ax[i], y = ax[j], z = ax[k];
        float s = __fadd_rn(__fadd_rn(__fmul_rn(x, x), __fmul_rn(y, y)), __fmul_rn(z, z));
        ok = (__fsqrt_rn(s) <= 6.0f);
    }
    unsigned int ballot = __ballot_sync(FULLM, ok);
    if ((threadIdx.x & 31) == 0) g_S0[g >> 5] = ballot;
}

// order-preserving float->uint key; 0 = "masked" (below all real keys)
__device__ __forceinline__ unsigned int f2key(float v)
{
    int i = __float_as_int(v);
    return (unsigned int)(i ^ ((i >> 31) | 0x80000000));
}
__device__ __forceinline__ float key2f(unsigned int k)
{
    int i = (k & 0x80000000u) ? (int)(k ^ 0x80000000u) : (int)~k;
    return __int_as_float(i);
}
__device__ __forceinline__ unsigned int sext_bit(unsigned int w, int bitpos)
{
    return (unsigned int)(((int)(w << (31 - bitpos))) >> 31);
}

// ---------------------------------------------------------------------------
// Kernel 2 (fused): pipelined 12-warp unmasked float4 chunk scan, then
// warp-0-only verified argmax + lazy Chebyshev NMS (warp-synchronous).
// ---------------------------------------------------------------------------
__global__ __launch_bounds__(NTHR, 4) void peaks_kernel(
    const float* __restrict__ density,   // [512, G]
    const float* __restrict__ grid_xyz,  // [G, 3]
    const float* __restrict__ Rmats,     // [128, 3, 3]
    const float* __restrict__ tpos,      // [128, 3]
    const float* __restrict__ node_mask, // [128]
    float* __restrict__ out)             // 16384 floats
{
    __shared__ unsigned int smask[NWORDS];  // live shifted bits
    __shared__ unsigned int ckey[CHUNKS];   // upper-bound chunk maxima
    __shared__ int          slist[CHUNKS];

    const int pair = blockIdx.x;            // n*4 + c
    const int tid  = threadIdx.x;
    const int lane = tid & 31;
    const int wid  = tid >> 5;
    const int aoff = (-pair) & 3;           // alignment shift (voxels)
    const float4* __restrict__ dens4 =
        (const float4*)(density + (size_t)pair * GTOT + aoff);
    const int nl = c_lists.n[aoff];

    // shifted mask on the fly: S_a[w] = (S0 >> a) across word boundary
    for (int w = tid; w < NWORDS; w += NTHR) {
        unsigned int lo = g_S0[w];
        unsigned int hi = (w + 1 < NWORDS) ? g_S0[w + 1] : 0u;
        smask[w] = __funnelshift_r(lo, hi, aoff);
    }
    for (int c = tid; c < CHUNKS; c += NTHR) ckey[c] = 0u;
    for (int e = tid; e < nl; e += NTHR) slist[e] = c_lists.list[aoff][e];
    __syncthreads();

    // ---- phase A: double-buffered unmasked per-chunk max (batch = 2) ----
    {
        int    cA0 = 0, cA1 = 0;
        float4 fA0, fA1;
        int e0 = wid * 2;
        if (e0 < nl) {
            cA0 = slist[e0];
            cA1 = slist[min(e0 + 1, nl - 1)];
            fA0 = __ldg(dens4 + cA0 * 32 + lane);
            fA1 = __ldg(dens4 + cA1 * 32 + lane);
        }
        for (; e0 < nl; e0 += NWARP * 2) {
            const int e1 = e0 + NWARP * 2;
            int    cB0 = 0, cB1 = 0;
            float4 fB0, fB1;
            if (e1 < nl) {                     // warp-uniform; loads precede REDUX below
                cB0 = slist[e1];
                cB1 = slist[min(e1 + 1, nl - 1)];
                fB0 = __ldg(dens4 + cB0 * 32 + lane);
                fB1 = __ldg(dens4 + cB1 * 32 + lane);
            }
            float m0 = fmaxf(fmaxf(fA0.x, fA0.y), fmaxf(fA0.z, fA0.w));
            unsigned int r0 = __reduce_max_sync(FULLM, f2key(m0));
            if (lane == 0) ckey[cA0] = r0;
            float m1 = fmaxf(fmaxf(fA1.x, fA1.y), fmaxf(fA1.z, fA1.w));
            unsigned int r1 = __reduce_max_sync(FULLM, f2key(m1));
            if (lane == 0 && e0 + 1 < nl) ckey[cA1] = r1;
            cA0 = cB0; cA1 = cB1; fA0 = fB0; fA1 = fB1;
        }
    }
    __syncthreads();

    if (wid != 0) return;   // warps 1-11 done; no further block barriers

    // ---- phase B: warp-synchronous verified argmax + lazy NMS ----
    float pk_score[KPK];
    int   pk_idx[KPK];
    int   pk_valid[KPK];

    for (int t = 0; t < KPK; ++t) {
        int gi = 0, valid = 0;
        float sc = 0.0f;
        for (;;) {
            // argmax over upper bounds (lowest chunk on ties)
            unsigned int bk = 0;
            int bc = 0x7FFFFFFF;
            for (int c = lane; c < CHUNKS; c += 32) {
                unsigned int k = ckey[c];
                if (k > bk) { bk = k; bc = c; }   // ascending: lowest c per lane
            }
            unsigned int fm = __reduce_max_sync(FULLM, bk);
            int cand = (bk == fm) ? bc : 0x7FFFFFFF;
            int fc = (int)__reduce_min_sync(FULLM, (unsigned int)cand);
            // masked verification of chunk fc
            float4 f = __ldg(dens4 + fc * 32 + lane);
            unsigned int mw = smask[fc * 4 + (lane >> 3)];
            int sh = (lane & 7) * 4;
            unsigned int k0 = f2key(f.x) & sext_bit(mw, sh + 0);
            unsigned int k1 = f2key(f.y) & sext_bit(mw, sh + 1);
            unsigned int k2 = f2key(f.z) & sext_bit(mw, sh + 2);
            unsigned int k3 = f2key(f.w) & sext_bit(mw, sh + 3);
            unsigned int bestk = k0; int besti = 0;
            if (k1 > bestk) { bestk = k1; besti = 1; }
            if (k2 > bestk) { bestk = k2; besti = 2; }
            if (k3 > bestk) { bestk = k3; besti = 3; }
            unsigned int mk = __reduce_max_sync(FULLM, bestk);
            if (mk == fm) {
                // accept: lowest-g argmax within chunk
                int gl = fc * 128 + lane * 4 + besti;
                int cg = (bestk == mk) ? gl : 0x7FFFFFFF;
                int gp = (int)__reduce_min_sync(FULLM, (unsigned int)cg);
                gi = gp + aoff;                  // absolute voxel index
                sc = key2f(fm);
                valid = (sc > VTH) ? 1 : 0;
                break;
            }
            // stale upper bound: decrease-key and retry
            if (lane == 0) ckey[fc] = mk;
            __syncwarp();
        }
        pk_score[t] = sc;
        pk_idx[t]   = gi;
        pk_valid[t] = valid;

        if (t < KPK - 1 && valid) {
            // clear bits in <=7x7x7 Chebyshev cube (shifted coords);
            // ckey stays a valid upper bound; pops self-correct.
            int ci = gi / NX2, cj = (gi / NXS) % NXS, ck = gi % NXS;
            int i0 = max(ci - 3, 0), i1 = min(ci + 3, NXS - 1);
            int j0 = max(cj - 3, 0), j1 = min(cj + 3, NXS - 1);
            int k0c = max(ck - 3, 0), k1c = min(ck + 3, NXS - 1);
            int nj = j1 - j0 + 1;
            int nrows = (i1 - i0 + 1) * nj;
            // rows >=41 bits apart -> never share a 32-bit word -> race-free
            for (int r = lane; r < nrows; r += 32) {
                int i = i0 + r / nj;
                int j = j0 + r % nj;
                int pb = i * NX2 + j * NXS + k0c - aoff;   // shifted position
                int pe = pb + (k1c - k0c);
                int w0 = pb >> 5, w1 = pe >> 5;
                unsigned int b0 = (unsigned int)(pb & 31);
                unsigned int b1 = (unsigned int)(pe & 31);
                unsigned int hi = (b1 == 31u) ? FULLM : ((1u << (b1 + 1)) - 1u);
                if (w0 == w1) {
                    unsigned int msk = hi & ~((1u << b0) - 1u);
                    smask[w0] &= ~msk;
                } else {
                    smask[w0] &= ((1u << b0) - 1u);
                    smask[w1] &= ~hi;
                }
            }
            __syncwarp();
        }
    }

    // ---- outputs (warp 0, lanes 0-3) ----
    // layout: coords_local[6144] | coords_global[6144] | scores[2048] | mask[2048]
    if (lane < KPK) {
        int k = lane;
        int n = pair >> 2;
        float nm = node_mask[n];
        int valid = pk_valid[k];
        float sc = valid ? pk_score[k] : NEGV;
        float x = 0.0f, y = 0.0f, z = 0.0f;
        if (valid) {
            int gi = pk_idx[k];
            x = grid_xyz[3 * gi + 0];
            y = grid_xyz[3 * gi + 1];
            z = grid_xyz[3 * gi + 2];
        }
        int o = (pair * KPK + k) * 3;
        out[o + 0] = x * nm;
        out[o + 1] = y * nm;
        out[o + 2] = z * nm;
        const float* R  = Rmats + n * 9;
        const float* tp = tpos + n * 3;
        float gx = R[0] * x + R[1] * y + R[2] * z + tp[0];
        float gy = R[3] * x + R[4] * y + R[5] * z + tp[1];
        float gz = R[6] * x + R[7] * y + R[8] * z + tp[2];
        out[6144 + o + 0] = gx * nm;
        out[6144 + o + 1] = gy * nm;
        out[6144 + o + 2] = gz * nm;
        out[12288 + pair * KPK + k] = sc * nm;
        out[14336 + pair * KPK + k] = (valid && nm != 0.0f) ? 1.0f : 0.0f;
    }
}

extern "C" void kernel_launch(void* const* d_in, const int* in_sizes, int n_in,
                              void* d_out, int out_size)
{
    // metadata order: density, grid_xyz, sphere_mask, coords_int, Rmats, tpos, node_mask
    const float* density   = (const float*)d_in[0];
    const float* grid_xyz  = (const float*)d_in[1];
    const float* Rmats     = (const float*)d_in[4];
    const float* tpos      = (const float*)d_in[5];
    const float* node_mask = (const float*)d_in[6];
    float* out = (float*)d_out;

    init_masks_kernel<<<270, 256>>>();
    peaks_kernel<<<NPAIR, NTHR>>>(density, grid_xyz, Rmats, tpos, node_mask, out);
}

// round 14
// speedup vs baseline: 1.1957x; 1.1957x over previous
#include <cuda_runtime.h>
#include <cuda_bf16.h>

// Problem constants
#define NXS    41
#define GTOT   68921          // 41^3
#define NX2    1681           // 41^2
#define NWORDS 2160           // dense mask words (tail zero)
#define CHUNKS 539            // chunk = 128 voxels (4 mask words)
#define KPK    4
#define NEGV   (-1.0e9f)
#define VTH    (-1.0e8f)
#define NPAIR  512            // B*N*C = 1*128*4
#define FULLM  0xffffffffu
#define NTHR   384            // 12 warps
#define NWARP  12

// Compile-time axis coords: float((i-20)*0.3 computed in double) — bit-exact vs numpy
struct AxTable { float v[NXS]; };
static constexpr AxTable make_ax()
{
    AxTable t{};
    for (int i = 0; i < NXS; ++i) t.v[i] = (float)((double)(i - 20) * 0.3);
    return t;
}
__constant__ AxTable c_ax = make_ax();

// Conservative in-sphere test (double, margin) — superset of the exact fp32 mask
static constexpr bool cons_in(int g)
{
    if (g < 0 || g >= GTOT) return false;
    int i = g / NX2, j = (g / NXS) % NXS, kk = g % NXS;
    double x = (i - 20) * 0.3, y = (j - 20) * 0.3, z = (kk - 20) * 0.3;
    return x * x + y * y + z * z <= 36.01;
}

// Compile-time conservative non-empty chunk lists per alignment shift a (0..3).
struct ChunkLists { short list[4][CHUNKS]; int n[4]; };
static constexpr ChunkLists make_lists()
{
    ChunkLists L{};
    for (int a = 0; a < 4; ++a) {
        int cnt = 0;
        for (int c = 0; c < CHUNKS; ++c) {
            bool ne = false;
            for (int p = c * 128; p < c * 128 + 128 && !ne; ++p) {
                if (p + a >= GTOT) break;
                ne = cons_in(p + a);
            }
            if (ne) { L.list[a][cnt] = (short)c; ++cnt; }
        }
        L.n[a] = cnt;
    }
    return L;
}
__constant__ ChunkLists c_lists = make_lists();

// Compile-time per-chunk quad masks: bit l set iff lane l's float4 (shifted
// positions c*128+l*4 .. +3) contains any conservatively-in-sphere voxel.
struct QMasks { unsigned int q[4][CHUNKS]; };
static constexpr QMasks make_qmasks()
{
    QMasks Q{};
    for (int a = 0; a < 4; ++a)
        for (int c = 0; c < CHUNKS; ++c) {
            unsigned int m = 0;
            for (int l = 0; l < 32; ++l) {
                bool any = false;
                for (int u = 0; u < 4 && !any; ++u)
                    any = cons_in(c * 128 + l * 4 + u + a);
                if (any) m |= (1u << l);
            }
            Q.q[a][c] = m;
        }
    return Q;
}
__constant__ QMasks c_qmasks = make_qmasks();

// Dense sphere mask (exact fp32 semantics), tail words zero
__device__ unsigned int g_S0[NWORDS];

// ---------------------------------------------------------------------------
// Kernel 1: dense sphere mask, numpy-identical fp32 op sequence
// ---------------------------------------------------------------------------
__global__ __launch_bounds__(256) void init_masks_kernel()
{
    __shared__ float ax[NXS];
    if (threadIdx.x < NXS) ax[threadIdx.x] = c_ax.v[threadIdx.x];
    __syncthreads();
    int g = blockIdx.x * 256 + threadIdx.x;    // 270*256 = 69120 = 2160 words
    bool ok = false;
    if (g < GTOT) {
        int i = g / NX2;
        int j = (g / NXS) % NXS;
        int k = g % NXS;
        float x = ax[i], y = ax[j], z = ax[k];
        float s = __fadd_rn(__fadd_rn(__fmul_rn(x, x), __fmul_rn(y, y)), __fmul_rn(z, z));
        ok = (__fsqrt_rn(s) <= 6.0f);
    }
    unsigned int ballot = __ballot_sync(FULLM, ok);
    if ((threadIdx.x & 31) == 0) g_S0[g >> 5] = ballot;
}

// order-preserving float->uint key; 0 = "masked" (below all real keys)
__device__ __forceinline__ unsigned int f2key(float v)
{
    int i = __float_as_int(v);
    return (unsigned int)(i ^ ((i >> 31) | 0x80000000));
}
__device__ __forceinline__ float key2f(unsigned int k)
{
    int i = (k & 0x80000000u) ? (int)(k ^ 0x80000000u) : (int)~k;
    return __int_as_float(i);
}
__device__ __forceinline__ unsigned int sext_bit(unsigned int w, int bitpos)
{
    return (unsigned int)(((int)(w << (31 - bitpos))) >> 31);
}

// ---------------------------------------------------------------------------
// Kernel 2 (fused): 12-warp quad-predicated float4 chunk scan, then warp-0-only
// verified argmax + lazy Chebyshev NMS (warp-synchronous, no block barriers).
// ---------------------------------------------------------------------------
__global__ __launch_bounds__(NTHR, 4) void peaks_kernel(
    const float* __restrict__ density,   // [512, G]
    const float* __restrict__ grid_xyz,  // [G, 3]
    const float* __restrict__ Rmats,     // [128, 3, 3]
    const float* __restrict__ tpos,      // [128, 3]
    const float* __restrict__ node_mask, // [128]
    float* __restrict__ out)             // 16384 floats
{
    __shared__ unsigned int smask[NWORDS];  // live shifted bits
    __shared__ unsigned int ckey[CHUNKS];   // upper-bound chunk maxima
    __shared__ int          slist[CHUNKS];  // listed chunk ids
    __shared__ unsigned int squad[CHUNKS];  // per-entry quad masks

    const int pair = blockIdx.x;            // n*4 + c
    const int tid  = threadIdx.x;
    const int lane = tid & 31;
    const int wid  = tid >> 5;
    const int aoff = (-pair) & 3;           // alignment shift (voxels)
    const float4* __restrict__ dens4 =
        (const float4*)(density + (size_t)pair * GTOT + aoff);
    const int nl = c_lists.n[aoff];
    const float NEGINF = __int_as_float(0xff800000);

    // shifted mask on the fly: S_a[w] = (S0 >> a) across word boundary
    for (int w = tid; w < NWORDS; w += NTHR) {
        unsigned int lo = g_S0[w];
        unsigned int hi = (w + 1 < NWORDS) ? g_S0[w + 1] : 0u;
        smask[w] = __funnelshift_r(lo, hi, aoff);
    }
    for (int c = tid; c < CHUNKS; c += NTHR) ckey[c] = 0u;
    for (int e = tid; e < nl; e += NTHR) {
        int c = c_lists.list[aoff][e];
        slist[e] = c;
        squad[e] = c_qmasks.q[aoff][c];
    }
    __syncthreads();

    // ---- phase A: quad-predicated per-chunk max over listed chunks ----
    for (int e0 = wid * 4; e0 < nl; e0 += NWARP * 4) {
        int    cc[4];
        float4 ff[4];
        #pragma unroll
        for (int b = 0; b < 4; ++b) {
            int e = min(e0 + b, nl - 1);          // dup-clamped tail
            cc[b] = slist[e];
            bool on = (squad[e] >> lane) & 1u;    // lane's quad intersects sphere
            ff[b] = on ? __ldg(dens4 + cc[b] * 32 + lane)
                       : make_float4(NEGINF, NEGINF, NEGINF, NEGINF);
        }
        #pragma unroll
        for (int b = 0; b < 4; ++b) {
            float m = fmaxf(fmaxf(ff[b].x, ff[b].y), fmaxf(ff[b].z, ff[b].w));
            unsigned int r = __reduce_max_sync(FULLM, f2key(m));
            if (lane == 0 && e0 + b < nl) ckey[cc[b]] = r;
        }
    }
    __syncthreads();

    if (wid != 0) return;   // warps 1-11 done; no further block barriers

    // ---- phase B: warp-synchronous verified argmax + lazy NMS ----
    float pk_score[KPK];
    int   pk_idx[KPK];
    int   pk_valid[KPK];

    for (int t = 0; t < KPK; ++t) {
        int gi = 0, valid = 0;
        float sc = 0.0f;
        for (;;) {
            // argmax over upper bounds (lowest chunk on ties)
            unsigned int bk = 0;
            int bc = 0x7FFFFFFF;
            for (int c = lane; c < CHUNKS; c += 32) {
                unsigned int k = ckey[c];
                if (k > bk) { bk = k; bc = c; }   // ascending: lowest c per lane
            }
            unsigned int fm = __reduce_max_sync(FULLM, bk);
            int cand = (bk == fm) ? bc : 0x7FFFFFFF;
            int fc = (int)__reduce_min_sync(FULLM, (unsigned int)cand);
            // masked verification of chunk fc (full load, exact fp32 mask)
            float4 f = __ldg(dens4 + fc * 32 + lane);
            unsigned int mw = smask[fc * 4 + (lane >> 3)];
            int sh = (lane & 7) * 4;
            unsigned int k0 = f2key(f.x) & sext_bit(mw, sh + 0);
            unsigned int k1 = f2key(f.y) & sext_bit(mw, sh + 1);
            unsigned int k2 = f2key(f.z) & sext_bit(mw, sh + 2);
            unsigned int k3 = f2key(f.w) & sext_bit(mw, sh + 3);
            unsigned int bestk = k0; int besti = 0;
            if (k1 > bestk) { bestk = k1; besti = 1; }
            if (k2 > bestk) { bestk = k2; besti = 2; }
            if (k3 > bestk) { bestk = k3; besti = 3; }
            unsigned int mk = __reduce_max_sync(FULLM, bestk);
            if (mk == fm) {
                // accept: lowest-g argmax within chunk
                int gl = fc * 128 + lane * 4 + besti;
                int cg = (bestk == mk) ? gl : 0x7FFFFFFF;
                int gp = (int)__reduce_min_sync(FULLM, (unsigned int)cg);
                gi = gp + aoff;                  // absolute voxel index
                sc = key2f(fm);
                valid = (sc > VTH) ? 1 : 0;
                break;
            }
            // stale upper bound: decrease-key and retry
            if (lane == 0) ckey[fc] = mk;
            __syncwarp();
        }
        pk_score[t] = sc;
        pk_idx[t]   = gi;
        pk_valid[t] = valid;

        if (t < KPK - 1 && valid) {
            // clear bits in <=7x7x7 Chebyshev cube (shifted coords);
            // ckey stays a valid upper bound; pops self-correct.
            int ci = gi / NX2, cj = (gi / NXS) % NXS, ck = gi % NXS;
            int i0 = max(ci - 3, 0), i1 = min(ci + 3, NXS - 1);
            int j0 = max(cj - 3, 0), j1 = min(cj + 3, NXS - 1);
            int k0c = max(ck - 3, 0), k1c = min(ck + 3, NXS - 1);
            int nj = j1 - j0 + 1;
            int nrows = (i1 - i0 + 1) * nj;
            // rows >=41 bits apart -> never share a 32-bit word -> race-free
            for (int r = lane; r < nrows; r += 32) {
                int i = i0 + r / nj;
                int j = j0 + r % nj;
                int pb = i * NX2 + j * NXS + k0c - aoff;   // shifted position
                int pe = pb + (k1c - k0c);
                int w0 = pb >> 5, w1 = pe >> 5;
                unsigned int b0 = (unsigned int)(pb & 31);
                unsigned int b1 = (unsigned int)(pe & 31);
                unsigned int hi = (b1 == 31u) ? FULLM : ((1u << (b1 + 1)) - 1u);
                if (w0 == w1) {
                    unsigned int msk = hi & ~((1u << b0) - 1u);
                    smask[w0] &= ~msk;
                } else {
                    smask[w0] &= ((1u << b0) - 1u);
                    smask[w1] &= ~hi;
                }
            }
            __syncwarp();
        }
    }

    // ---- outputs (warp 0, lanes 0-3) ----
    // layout: coords_local[6144] | coords_global[6144] | scores[2048] | mask[2048]
    if (lane < KPK) {
        int k = lane;
        int n = pair >> 2;
        float nm = node_mask[n];
        int valid = pk_valid[k];
        float sc = valid ? pk_score[k] : NEGV;
        float x = 0.0f, y = 0.0f, z = 0.0f;
        if (valid) {
            int gi = pk_idx[k];
            x = grid_xyz[3 * gi + 0];
            y = grid_xyz[3 * gi + 1];
            z = grid_xyz[3 * gi + 2];
        }
        int o = (pair * KPK + k) * 3;
        out[o + 0] = x * nm;
        out[o + 1] = y * nm;
        out[o + 2] = z * nm;
        const float* R  = Rmats + n * 9;
        const float* tp = tpos + n * 3;
        float gx = R[0] * x + R[1] * y + R[2] * z + tp[0];
        float gy = R[3] * x + R[4] * y + R[5] * z + tp[1];
        float gz = R[6] * x + R[7] * y + R[8] * z + tp[2];
        out[6144 + o + 0] = gx * nm;
        out[6144 + o + 1] = gy * nm;
        out[6144 + o + 2] = gz * nm;
        out[12288 + pair * KPK + k] = sc * nm;
        out[14336 + pair * KPK + k] = (valid && nm != 0.0f) ? 1.0f : 0.0f;
    }
}

extern "C" void kernel_launch(void* const* d_in, const int* in_sizes, int n_in,
                              void* d_out, int out_size)
{
    // metadata order: density, grid_xyz, sphere_mask, coords_int, Rmats, tpos, node_mask
    const float* density   = (const float*)d_in[0];
    const float* grid_xyz  = (const float*)d_in[1];
    const float* Rmats     = (const float*)d_in[4];
    const float* tpos      = (const float*)d_in[5];
    const float* node_mask = (const float*)d_in[6];
    float* out = (float*)d_out;

    init_masks_kernel<<<270, 256>>>();
    peaks_kernel<<<NPAIR, NTHR>>>(density, grid_xyz, Rmats, tpos, node_mask, out);
}